// round 6
// baseline (speedup 1.0000x reference)
#include <cuda_runtime.h>
#include <cstdint>
#include <cstddef>

#define BATCH 64
#define SEQ   2048
#define IND   128
#define HID   256
#define OUTD  64
#define M_ROWS (SEQ*BATCH)

typedef unsigned long long ull;

// ---------------- scratch ----------------
__device__ float g_bufA[(size_t)SEQ * BATCH * HID];
__device__ float g_bufH[(size_t)SEQ * BATCH * HID];
__device__ float g_T1[HID * HID];
__device__ float g_Wc[OUTD * HID];
__device__ float g_b12[HID];
__device__ float g_bc[OUTD];

// ---------------- f32x2 helpers ----------------
__device__ __forceinline__ void ffma2(ull& acc, ull a, ull b) {
    asm("fma.rn.f32x2 %0, %1, %2, %0;" : "+l"(acc) : "l"(a), "l"(b));
}
__device__ __forceinline__ ull pack2(float x, float y) {
    ull r; asm("mov.b64 %0, {%1,%2};" : "=l"(r) : "f"(x), "f"(y)); return r;
}
__device__ __forceinline__ float2 unpack2(ull v) {
    float2 r; asm("mov.b64 {%0,%1}, %2;" : "=f"(r.x), "=f"(r.y) : "l"(v)); return r;
}
__device__ __forceinline__ void lds_v2u64(ull& a, ull& b, uint32_t addr) {
    asm volatile("ld.shared.v2.u64 {%0,%1}, [%2];" : "=l"(a), "=l"(b) : "r"(addr));
}
// fast tanh: 1 - 2/(exp(2x)+1); MUFU-based, rel err ~1e-6, saturates correctly
__device__ __forceinline__ float tanh_fast(float x) {
    float e = __expf(2.f * x);
    return 1.f - __fdividef(2.f, e + 1.f);
}

// ---------------- head folding ----------------
__global__ void combine1_kernel(const float* __restrict__ fc2W, const float* __restrict__ fc1W,
                                const float* __restrict__ fc1b, const float* __restrict__ fc2b) {
    int i = blockIdx.x, k = threadIdx.x;
    float acc = 0.f;
    for (int j = 0; j < HID; ++j) acc += fc2W[i * HID + j] * fc1W[j * HID + k];
    g_T1[i * HID + k] = acc;
    if (k == 0) {
        float s = 0.f;
        for (int j = 0; j < HID; ++j) s += fc2W[i * HID + j] * fc1b[j];
        g_b12[i] = s + fc2b[i];
    }
}
__global__ void combine2_kernel(const float* __restrict__ fc3W, const float* __restrict__ fc3b) {
    int o = blockIdx.x, k = threadIdx.x;
    float acc = 0.f;
    for (int j = 0; j < HID; ++j) acc += fc3W[o * HID + j] * g_T1[j * HID + k];
    g_Wc[o * HID + k] = acc;
    if (k == 0) {
        float s = 0.f;
        for (int j = 0; j < HID; ++j) s += fc3W[o * HID + j] * g_b12[j];
        g_bc[o] = s + fc3b[o];
    }
}

// ---------------- f32x2 SIMT GEMM ----------------
template<int TN, int MT, int AMODE, int OMODE>
__global__ void __launch_bounds__(256)
gemm_kernel(const float* __restrict__ Ap, const float* __restrict__ Bw,
            const float* __restrict__ bias1, const float* __restrict__ bias2,
            float* __restrict__ Cp, int K) {
    __shared__ __align__(16) float As[16][128];
    __shared__ __align__(16) float Bs[16][TN];
    constexpr int NX = TN / 8;
    const int tid = threadIdx.x;
    const int bm = blockIdx.x * 128;
    const int bn = blockIdx.y * TN;
    const int tx = tid % NX, ty = tid / NX;

    const float* arow[2]; int amm[2], akq[2];
#pragma unroll
    for (int it = 0; it < 2; ++it) {
        int slot = tid + it * 256;
        amm[it] = slot >> 2; akq[it] = slot & 3;
        int m = bm + amm[it];
        if (AMODE) arow[it] = Ap + ((size_t)(m & 63) * SEQ + (m >> 6)) * K;
        else       arow[it] = Ap + (size_t)m * K;
    }
    constexpr int BLD = TN / 64;
    const float* brow[BLD]; int bnn[BLD], bkq[BLD];
#pragma unroll
    for (int it = 0; it < BLD; ++it) {
        int slot = tid + it * 256;
        bnn[it] = slot >> 2; bkq[it] = slot & 3;
        brow[it] = Bw + (size_t)(bn + bnn[it]) * K;
    }

    ull acc[MT][4];
#pragma unroll
    for (int i = 0; i < MT; ++i)
#pragma unroll
        for (int j = 0; j < 4; ++j) acc[i][j] = 0ull;

    uint32_t bs_base = (uint32_t)__cvta_generic_to_shared(&Bs[0][0]);

    for (int k0 = 0; k0 < K; k0 += 16) {
#pragma unroll
        for (int it = 0; it < 2; ++it) {
            float4 v = *(const float4*)(arow[it] + k0 + akq[it] * 4);
            As[akq[it] * 4 + 0][amm[it]] = v.x;
            As[akq[it] * 4 + 1][amm[it]] = v.y;
            As[akq[it] * 4 + 2][amm[it]] = v.z;
            As[akq[it] * 4 + 3][amm[it]] = v.w;
        }
#pragma unroll
        for (int it = 0; it < BLD; ++it) {
            float4 v = *(const float4*)(brow[it] + k0 + bkq[it] * 4);
            Bs[bkq[it] * 4 + 0][bnn[it]] = v.x;
            Bs[bkq[it] * 4 + 1][bnn[it]] = v.y;
            Bs[bkq[it] * 4 + 2][bnn[it]] = v.z;
            Bs[bkq[it] * 4 + 3][bnn[it]] = v.w;
        }
        __syncthreads();
#pragma unroll
        for (int kk = 0; kk < 16; ++kk) {
            ull b0, b1, b2, b3;
            uint32_t ba = bs_base + (uint32_t)((kk * TN + tx * 8) * 4);
            lds_v2u64(b0, b1, ba);
            lds_v2u64(b2, b3, ba + 16);
            float av[MT];
#pragma unroll
            for (int q = 0; q < MT; q += 4) {
                float4 a4 = *(const float4*)&As[kk][ty * MT + q];
                av[q] = a4.x; av[q + 1] = a4.y; av[q + 2] = a4.z; av[q + 3] = a4.w;
            }
#pragma unroll
            for (int i = 0; i < MT; ++i) {
                ull ad = pack2(av[i], av[i]);
                ffma2(acc[i][0], ad, b0);
                ffma2(acc[i][1], ad, b1);
                ffma2(acc[i][2], ad, b2);
                ffma2(acc[i][3], ad, b3);
            }
        }
        __syncthreads();
    }

    float bb[8];
#pragma unroll
    for (int j = 0; j < 8; ++j) {
        int n = bn + tx * 8 + j;
        float v = bias1 ? bias1[n] : 0.f;
        if (bias2) v += bias2[n];
        bb[j] = v;
    }
#pragma unroll
    for (int i = 0; i < MT; ++i) {
        int m = bm + ty * MT + i;
        float2 p0 = unpack2(acc[i][0]), p1 = unpack2(acc[i][1]);
        float2 p2 = unpack2(acc[i][2]), p3 = unpack2(acc[i][3]);
        float4 v0 = {p0.x + bb[0], p0.y + bb[1], p1.x + bb[2], p1.y + bb[3]};
        float4 v1 = {p2.x + bb[4], p2.y + bb[5], p3.x + bb[6], p3.y + bb[7]};
        float* dst;
        if (OMODE) dst = Cp + ((size_t)(m & 63) * SEQ + (m >> 6)) * OUTD + bn + tx * 8;
        else       dst = Cp + (size_t)m * ((size_t)gridDim.y * TN) + bn + tx * 8;
        *(float4*)dst = v0;
        *(float4*)(dst + 4) = v1;
    }
}

// ---------------- persistent RNN scan, k-split + 2-stream interleave ----------------
// 2-CTA cluster handles TWO batch elements (streams). Thread tid holds
// W[tid][rank*128 .. rank*128+128) once (shared across streams). Per step,
// per stream: dot over local h-half, push partials for peer rows via DSMEM;
// stream 0's DSMEM flight hides under stream 1's dot. Own rows wait + tanh.
__device__ __forceinline__ void cluster_sync_() {
    asm volatile("barrier.cluster.arrive.aligned;" ::: "memory");
    asm volatile("barrier.cluster.wait.aligned;" ::: "memory");
}
__device__ __forceinline__ void mbar_wait_cluster(uint32_t mb, int ph) {
    asm volatile(
        "{\n\t.reg .pred P;\n"
        "W1_%=:\n\t"
        "mbarrier.try_wait.parity.acquire.cluster.shared::cta.b64 P, [%0], %1, 0x989680;\n\t"
        "@P bra W2_%=;\n\t"
        "bra W1_%=;\n"
        "W2_%=:\n\t}"
        :: "r"(mb), "r"(ph) : "memory");
}

__global__ void __cluster_dims__(2, 1, 1) __launch_bounds__(256, 1)
scan_kernel(const float* __restrict__ A, const float* __restrict__ W, float* __restrict__ Hout) {
    __shared__ __align__(16) float h_sm[2][2][128];     // [stream][phase][j]
    __shared__ __align__(16) float recv_sm[2][2][128];  // [stream][phase][j]
    __shared__ __align__(8) ull mbar[4];                // [stream*2 + phase]
    const int tid = threadIdx.x;
    uint32_t rank;
    asm("mov.u32 %0, %%cluster_ctarank;" : "=r"(rank));
    const int cid = blockIdx.x >> 1;                    // 0..31
    const int jl = tid & 127;
    const bool own = ((uint32_t)(tid >> 7) == rank);    // warp-uniform

    // register-resident W slice: row tid, k in [rank*128, rank*128+128)
    ull wreg[64];
    {
        const float* ws = W + (size_t)tid * HID + rank * 128;
#pragma unroll
        for (int i = 0; i < 64; i += 2) {
            float4 v = *(const float4*)(ws + i * 2);
            wreg[i] = pack2(v.x, v.y); wreg[i + 1] = pack2(v.z, v.w);
        }
    }

    uint32_t h_local = (uint32_t)__cvta_generic_to_shared(&h_sm[0][0][0]);
    uint32_t recv_local = (uint32_t)__cvta_generic_to_shared(&recv_sm[0][0][0]);
    uint32_t mb_local = (uint32_t)__cvta_generic_to_shared(&mbar[0]);
    uint32_t recv_peer, mb_peer;
    asm("mapa.shared::cluster.u32 %0, %1, %2;" : "=r"(recv_peer) : "r"(recv_local), "r"(rank ^ 1u));
    asm("mapa.shared::cluster.u32 %0, %1, %2;" : "=r"(mb_peer) : "r"(mb_local), "r"(rank ^ 1u));

    if (tid < 4) {
        asm volatile("mbarrier.init.shared.b64 [%0], %1;"
                     :: "r"(mb_local + tid * 8), "r"(4) : "memory");
    }
    __syncthreads();
    cluster_sync_();  // peer mbarriers live before any remote arrive

    const int b0 = cid * 2, b1 = cid * 2 + 1;
    const float* Ab0 = A + (size_t)b0 * HID + tid;   // only used by own rows
    const float* Ab1 = A + (size_t)b1 * HID + tid;
    float* Hb0 = Hout + (size_t)b0 * HID + tid;
    float* Hb1 = Hout + (size_t)b1 * HID + tid;

    float ac0 = 0.f, an0 = 0.f, ac1 = 0.f, an1 = 0.f;
    // ---- t = 0: h = tanh(A[0]) ----
    if (own) {
        ac0 = __ldg(Ab0); ac1 = __ldg(Ab1);
        float h0 = tanh_fast(ac0), h1 = tanh_fast(ac1);
        h_sm[0][1][jl] = h0; h_sm[1][1][jl] = h1;
        Hb0[0] = h0; Hb1[0] = h1;
        an0 = __ldg(Ab0 + (size_t)BATCH * HID);
        an1 = __ldg(Ab1 + (size_t)BATCH * HID);
    }
    __syncthreads();

    int ph0 = 0, ph1 = 0;
    for (int t = 1; t < SEQ; ++t) {
        const int p = t & 1;
        ac0 = an0; ac1 = an1;
        if (own) {
            int tn = (t + 1 < SEQ) ? (t + 1) : (SEQ - 1);
            an0 = __ldg(Ab0 + (size_t)tn * (BATCH * HID));
            an1 = __ldg(Ab1 + (size_t)tn * (BATCH * HID));
        }
        // ---- stream 0 dot ----
        uint32_t hb0 = h_local + (uint32_t)(p * 128 * 4);
        ull a0 = 0ull, a1 = 0ull, a2 = 0ull, a3 = 0ull;
#pragma unroll
        for (int i = 0; i < 32; ++i) {
            ull x0, x1;
            lds_v2u64(x0, x1, hb0 + (uint32_t)(i * 16));
            if (i & 1) { ffma2(a2, wreg[2 * i], x0); ffma2(a3, wreg[2 * i + 1], x1); }
            else       { ffma2(a0, wreg[2 * i], x0); ffma2(a1, wreg[2 * i + 1], x1); }
        }
        float2 s0 = unpack2(a0), s1 = unpack2(a1), s2 = unpack2(a2), s3 = unpack2(a3);
        float part0 = ((s0.x + s0.y) + (s1.x + s1.y)) + ((s2.x + s2.y) + (s3.x + s3.y));
        if (!own) {
            uint32_t ra = recv_peer + (uint32_t)((p * 128 + jl) * 4);
            asm volatile("st.shared::cluster.f32 [%0], %1;" :: "r"(ra), "f"(part0) : "memory");
            __syncwarp();
            if ((tid & 31) == 0) {
                asm volatile("mbarrier.arrive.release.cluster.shared::cluster.b64 _, [%0];"
                             :: "r"(mb_peer + (uint32_t)(p * 8)) : "memory");
            }
        }
        // ---- stream 1 dot (stream 0's DSMEM flight hides under this) ----
        uint32_t hb1 = h_local + (uint32_t)((2 + p) * 128 * 4);
        ull c0 = 0ull, c1 = 0ull, c2 = 0ull, c3 = 0ull;
#pragma unroll
        for (int i = 0; i < 32; ++i) {
            ull x0, x1;
            lds_v2u64(x0, x1, hb1 + (uint32_t)(i * 16));
            if (i & 1) { ffma2(c2, wreg[2 * i], x0); ffma2(c3, wreg[2 * i + 1], x1); }
            else       { ffma2(c0, wreg[2 * i], x0); ffma2(c1, wreg[2 * i + 1], x1); }
        }
        float2 u0 = unpack2(c0), u1 = unpack2(c1), u2 = unpack2(c2), u3 = unpack2(c3);
        float part1 = ((u0.x + u0.y) + (u1.x + u1.y)) + ((u2.x + u2.y) + (u3.x + u3.y));
        if (!own) {
            uint32_t ra = recv_peer + (uint32_t)(((2 + p) * 128 + jl) * 4);
            asm volatile("st.shared::cluster.f32 [%0], %1;" :: "r"(ra), "f"(part1) : "memory");
            __syncwarp();
            if ((tid & 31) == 0) {
                asm volatile("mbarrier.arrive.release.cluster.shared::cluster.b64 _, [%0];"
                             :: "r"(mb_peer + (uint32_t)((2 + p) * 8)) : "memory");
            }
        } else {
            const int ph = p ? ph1 : ph0;
            // stream 0 finalize
            mbar_wait_cluster(mb_local + (uint32_t)(p * 8), ph);
            float h0 = tanh_fast(part0 + recv_sm[0][p][jl] + ac0);
            h_sm[0][p ^ 1][jl] = h0;
            Hb0[(size_t)t * (BATCH * HID)] = h0;
            // stream 1 finalize
            mbar_wait_cluster(mb_local + (uint32_t)((2 + p) * 8), ph);
            float h1 = tanh_fast(part1 + recv_sm[1][p][jl] + ac1);
            h_sm[1][p ^ 1][jl] = h1;
            Hb1[(size_t)t * (BATCH * HID)] = h1;
            if (p) ph1 ^= 1; else ph0 ^= 1;
        }
        __syncthreads();  // new h visible; closes reuse window on phase-p buffers
    }
    cluster_sync_();  // keep smem alive for in-flight peer traffic
}

// ---------------- launcher ----------------
extern "C" void kernel_launch(void* const* d_in, const int* in_sizes, int n_in,
                              void* d_out, int out_size) {
    const float* x    = (const float*)d_in[0];
    const float* U0   = (const float*)d_in[1];
    const float* bU0  = (const float*)d_in[2];
    const float* W0   = (const float*)d_in[3];
    const float* bW0  = (const float*)d_in[4];
    const float* U1   = (const float*)d_in[5];
    const float* bU1  = (const float*)d_in[6];
    const float* W1   = (const float*)d_in[7];
    const float* bW1  = (const float*)d_in[8];
    const float* fc1W = (const float*)d_in[9];
    const float* fc1b = (const float*)d_in[10];
    const float* fc2W = (const float*)d_in[11];
    const float* fc2b = (const float*)d_in[12];
    const float* fc3W = (const float*)d_in[13];
    const float* fc3b = (const float*)d_in[14];
    float* out = (float*)d_out;

    float *pA, *pH, *pWc, *pbc;
    cudaGetSymbolAddress((void**)&pA, g_bufA);
    cudaGetSymbolAddress((void**)&pH, g_bufH);
    cudaGetSymbolAddress((void**)&pWc, g_Wc);
    cudaGetSymbolAddress((void**)&pbc, g_bc);

    combine1_kernel<<<HID, HID>>>(fc2W, fc1W, fc1b, fc2b);
    combine2_kernel<<<OUTD, HID>>>(fc3W, fc3b);

    // A0[t,b,:] = x[b,t,:] @ U0^T + bU0 + bW0
    gemm_kernel<128, 8, 1, 0><<<dim3(M_ROWS / 128, HID / 128), 256>>>(x, U0, bU0, bW0, pA, IND);
    scan_kernel<<<BATCH, 256>>>(pA, W0, pH);   // 32 clusters x 2 CTAs, 2 streams each
    // A1 = h0_all @ U1^T + bU1 + bW1
    gemm_kernel<128, 8, 0, 0><<<dim3(M_ROWS / 128, HID / 128), 256>>>(pH, U1, bU1, bW1, pA, HID);
    scan_kernel<<<BATCH, 256>>>(pA, W1, pH);
    // head: out[b,t,:] = outs[t,b,:] @ Wc^T + bc (N=64)
    gemm_kernel<64, 4, 0, 1><<<dim3(M_ROWS / 128, 1), 256>>>(pH, pWc, pbc, nullptr, out, HID);
}

// round 7
// speedup vs baseline: 1.3825x; 1.3825x over previous
#include <cuda_runtime.h>
#include <cstdint>
#include <cstddef>

#define BATCH 64
#define SEQ   2048
#define IND   128
#define HID   256
#define OUTD  64
#define M_ROWS (SEQ*BATCH)

typedef unsigned long long ull;

// ---------------- scratch ----------------
__device__ float g_bufA[(size_t)SEQ * BATCH * HID];
__device__ float g_bufH[(size_t)SEQ * BATCH * HID];
__device__ float g_T1[HID * HID];
__device__ float g_Wc[OUTD * HID];
__device__ float g_b12[HID];
__device__ float g_bc[OUTD];

// ---------------- f32x2 helpers ----------------
__device__ __forceinline__ void ffma2(ull& acc, ull a, ull b) {
    asm("fma.rn.f32x2 %0, %1, %2, %0;" : "+l"(acc) : "l"(a), "l"(b));
}
__device__ __forceinline__ ull pack2(float x, float y) {
    ull r; asm("mov.b64 %0, {%1,%2};" : "=l"(r) : "f"(x), "f"(y)); return r;
}
__device__ __forceinline__ float2 unpack2(ull v) {
    float2 r; asm("mov.b64 {%0,%1}, %2;" : "=f"(r.x), "=f"(r.y) : "l"(v)); return r;
}
__device__ __forceinline__ void lds_v2u64(ull& a, ull& b, uint32_t addr) {
    asm volatile("ld.shared.v2.u64 {%0,%1}, [%2];" : "=l"(a), "=l"(b) : "r"(addr));
}
// fast tanh: 1 - 2/(exp(2x)+1); MUFU-based, rel err ~1e-6, saturates correctly
__device__ __forceinline__ float tanh_fast(float x) {
    float e = __expf(2.f * x);
    return 1.f - __fdividef(2.f, e + 1.f);
}

// ---------------- head folding ----------------
__global__ void combine1_kernel(const float* __restrict__ fc2W, const float* __restrict__ fc1W,
                                const float* __restrict__ fc1b, const float* __restrict__ fc2b) {
    int i = blockIdx.x, k = threadIdx.x;
    float acc = 0.f;
    for (int j = 0; j < HID; ++j) acc += fc2W[i * HID + j] * fc1W[j * HID + k];
    g_T1[i * HID + k] = acc;
    if (k == 0) {
        float s = 0.f;
        for (int j = 0; j < HID; ++j) s += fc2W[i * HID + j] * fc1b[j];
        g_b12[i] = s + fc2b[i];
    }
}
__global__ void combine2_kernel(const float* __restrict__ fc3W, const float* __restrict__ fc3b) {
    int o = blockIdx.x, k = threadIdx.x;
    float acc = 0.f;
    for (int j = 0; j < HID; ++j) acc += fc3W[o * HID + j] * g_T1[j * HID + k];
    g_Wc[o * HID + k] = acc;
    if (k == 0) {
        float s = 0.f;
        for (int j = 0; j < HID; ++j) s += fc3W[o * HID + j] * g_b12[j];
        g_bc[o] = s + fc3b[o];
    }
}

// ---------------- f32x2 SIMT GEMM (unchanged from R4 baseline) ----------------
template<int TN, int MT, int AMODE, int OMODE>
__global__ void __launch_bounds__(256)
gemm_kernel(const float* __restrict__ Ap, const float* __restrict__ Bw,
            const float* __restrict__ bias1, const float* __restrict__ bias2,
            float* __restrict__ Cp, int K) {
    __shared__ __align__(16) float As[16][128];
    __shared__ __align__(16) float Bs[16][TN];
    constexpr int NX = TN / 8;
    const int tid = threadIdx.x;
    const int bm = blockIdx.x * 128;
    const int bn = blockIdx.y * TN;
    const int tx = tid % NX, ty = tid / NX;

    const float* arow[2]; int amm[2], akq[2];
#pragma unroll
    for (int it = 0; it < 2; ++it) {
        int slot = tid + it * 256;
        amm[it] = slot >> 2; akq[it] = slot & 3;
        int m = bm + amm[it];
        if (AMODE) arow[it] = Ap + ((size_t)(m & 63) * SEQ + (m >> 6)) * K;
        else       arow[it] = Ap + (size_t)m * K;
    }
    constexpr int BLD = TN / 64;
    const float* brow[BLD]; int bnn[BLD], bkq[BLD];
#pragma unroll
    for (int it = 0; it < BLD; ++it) {
        int slot = tid + it * 256;
        bnn[it] = slot >> 2; bkq[it] = slot & 3;
        brow[it] = Bw + (size_t)(bn + bnn[it]) * K;
    }

    ull acc[MT][4];
#pragma unroll
    for (int i = 0; i < MT; ++i)
#pragma unroll
        for (int j = 0; j < 4; ++j) acc[i][j] = 0ull;

    uint32_t bs_base = (uint32_t)__cvta_generic_to_shared(&Bs[0][0]);

    for (int k0 = 0; k0 < K; k0 += 16) {
#pragma unroll
        for (int it = 0; it < 2; ++it) {
            float4 v = *(const float4*)(arow[it] + k0 + akq[it] * 4);
            As[akq[it] * 4 + 0][amm[it]] = v.x;
            As[akq[it] * 4 + 1][amm[it]] = v.y;
            As[akq[it] * 4 + 2][amm[it]] = v.z;
            As[akq[it] * 4 + 3][amm[it]] = v.w;
        }
#pragma unroll
        for (int it = 0; it < BLD; ++it) {
            float4 v = *(const float4*)(brow[it] + k0 + bkq[it] * 4);
            Bs[bkq[it] * 4 + 0][bnn[it]] = v.x;
            Bs[bkq[it] * 4 + 1][bnn[it]] = v.y;
            Bs[bkq[it] * 4 + 2][bnn[it]] = v.z;
            Bs[bkq[it] * 4 + 3][bnn[it]] = v.w;
        }
        __syncthreads();
#pragma unroll
        for (int kk = 0; kk < 16; ++kk) {
            ull b0, b1, b2, b3;
            uint32_t ba = bs_base + (uint32_t)((kk * TN + tx * 8) * 4);
            lds_v2u64(b0, b1, ba);
            lds_v2u64(b2, b3, ba + 16);
            float av[MT];
#pragma unroll
            for (int q = 0; q < MT; q += 4) {
                float4 a4 = *(const float4*)&As[kk][ty * MT + q];
                av[q] = a4.x; av[q + 1] = a4.y; av[q + 2] = a4.z; av[q + 3] = a4.w;
            }
#pragma unroll
            for (int i = 0; i < MT; ++i) {
                ull ad = pack2(av[i], av[i]);
                ffma2(acc[i][0], ad, b0);
                ffma2(acc[i][1], ad, b1);
                ffma2(acc[i][2], ad, b2);
                ffma2(acc[i][3], ad, b3);
            }
        }
        __syncthreads();
    }

    float bb[8];
#pragma unroll
    for (int j = 0; j < 8; ++j) {
        int n = bn + tx * 8 + j;
        float v = bias1 ? bias1[n] : 0.f;
        if (bias2) v += bias2[n];
        bb[j] = v;
    }
#pragma unroll
    for (int i = 0; i < MT; ++i) {
        int m = bm + ty * MT + i;
        float2 p0 = unpack2(acc[i][0]), p1 = unpack2(acc[i][1]);
        float2 p2 = unpack2(acc[i][2]), p3 = unpack2(acc[i][3]);
        float4 v0 = {p0.x + bb[0], p0.y + bb[1], p1.x + bb[2], p1.y + bb[3]};
        float4 v1 = {p2.x + bb[4], p2.y + bb[5], p3.x + bb[6], p3.y + bb[7]};
        float* dst;
        if (OMODE) dst = Cp + ((size_t)(m & 63) * SEQ + (m >> 6)) * OUTD + bn + tx * 8;
        else       dst = Cp + (size_t)m * ((size_t)gridDim.y * TN) + bn + tx * 8;
        *(float4*)dst = v0;
        *(float4*)(dst + 4) = v1;
    }
}

// ---------------- persistent RNN scan, k-split + lane-pair dot ----------------
// 2-CTA cluster per batch. 512 threads/CTA. Warp w handles rows [w*16,(w+1)*16);
// each row is computed by a lane pair (l, l+16): lane half 0 takes k-subchunk
// [rank*128, +64), half 1 takes [rank*128+64, +64). 32 ull (64 floats) of W per
// thread in registers. Dot = 16 LDS.v2 + 32 ffma2 + shfl.xor(16) combine.
// Partials for peer-owned rows pushed via DSMEM (8 pusher warps, mbar count 8);
// owners wait + tanh. h never crosses the cluster.
__device__ __forceinline__ void cluster_sync_() {
    asm volatile("barrier.cluster.arrive.aligned;" ::: "memory");
    asm volatile("barrier.cluster.wait.aligned;" ::: "memory");
}
__device__ __forceinline__ void mbar_wait_cluster(uint32_t mb, int ph) {
    asm volatile(
        "{\n\t.reg .pred P;\n"
        "W1_%=:\n\t"
        "mbarrier.try_wait.parity.acquire.cluster.shared::cta.b64 P, [%0], %1, 0x989680;\n\t"
        "@P bra W2_%=;\n\t"
        "bra W1_%=;\n"
        "W2_%=:\n\t}"
        :: "r"(mb), "r"(ph) : "memory");
}

__global__ void __cluster_dims__(2, 1, 1) __launch_bounds__(512, 1)
scan_kernel(const float* __restrict__ A, const float* __restrict__ W, float* __restrict__ Hout) {
    __shared__ __align__(16) float h_sm[2][128];     // local h half, double buffered
    __shared__ __align__(16) float recv_sm[2][128];  // incoming partials for own rows
    __shared__ __align__(8) ull mbar[2];
    const int tid = threadIdx.x;
    uint32_t rank;
    asm("mov.u32 %0, %%cluster_ctarank;" : "=r"(rank));
    const int b = blockIdx.x >> 1;
    const int w = tid >> 5;
    const int lane = tid & 31;
    const int lsub = lane & 15;
    const bool lhalf = (lane < 16);
    const int row = w * 16 + lsub;          // global output row 0..255
    const int jl = row & 127;               // index within owning CTA's half
    const bool own = ((w >> 3) == (int)rank);  // warp-uniform
    const int ksub = (lane >> 4) * 64;      // this lane's 64-wide k-subchunk

    // register-resident W: row `row`, k in [rank*128 + ksub, +64)
    ull wreg[32];
    {
        const float* ws = W + (size_t)row * HID + rank * 128 + ksub;
#pragma unroll
        for (int i = 0; i < 32; i += 2) {
            float4 v = *(const float4*)(ws + i * 2);
            wreg[i] = pack2(v.x, v.y); wreg[i + 1] = pack2(v.z, v.w);
        }
    }

    uint32_t h_local = (uint32_t)__cvta_generic_to_shared(&h_sm[0][0]);
    uint32_t recv_local = (uint32_t)__cvta_generic_to_shared(&recv_sm[0][0]);
    uint32_t mb_local = (uint32_t)__cvta_generic_to_shared(&mbar[0]);
    uint32_t recv_peer, mb_peer;
    asm("mapa.shared::cluster.u32 %0, %1, %2;" : "=r"(recv_peer) : "r"(recv_local), "r"(rank ^ 1u));
    asm("mapa.shared::cluster.u32 %0, %1, %2;" : "=r"(mb_peer) : "r"(mb_local), "r"(rank ^ 1u));

    if (tid < 2) {
        asm volatile("mbarrier.init.shared.b64 [%0], %1;"
                     :: "r"(mb_local + tid * 8), "r"(8) : "memory");  // 8 pusher warps
    }
    __syncthreads();
    cluster_sync_();  // peer mbarriers live before any remote arrive

    const float* Abase = A + (size_t)b * HID + row;   // used by own rows, lane<16
    float* Hbase = Hout + (size_t)b * HID + row;

    float acur = 0.f, anext = 0.f;
    // ---- t = 0: h = tanh(A[0]) ----
    if (own && lhalf) {
        acur = __ldg(Abase);
        float hv = tanh_fast(acur);
        h_sm[1][jl] = hv;
        Hbase[0] = hv;
        anext = __ldg(Abase + (size_t)BATCH * HID);
    }
    __syncthreads();

    int ph0 = 0, ph1 = 0;
    for (int t = 1; t < SEQ; ++t) {
        const int p = t & 1;
        acur = anext;
        if (own && lhalf) {
            int tn = (t + 1 < SEQ) ? (t + 1) : (SEQ - 1);
            anext = __ldg(Abase + (size_t)tn * (BATCH * HID));
        }
        // ---- dot over this lane's 64-wide h-subchunk (h[t-1] in h_sm[p]) ----
        uint32_t hb = h_local + (uint32_t)((p * 128 + ksub) * 4);
        ull a0 = 0ull, a1 = 0ull, a2 = 0ull, a3 = 0ull;
#pragma unroll
        for (int i = 0; i < 16; ++i) {           // 16 iters x 4 floats = 64 h values
            ull x0, x1;
            lds_v2u64(x0, x1, hb + (uint32_t)(i * 16));
            if (i & 1) { ffma2(a2, wreg[2 * i], x0); ffma2(a3, wreg[2 * i + 1], x1); }
            else       { ffma2(a0, wreg[2 * i], x0); ffma2(a1, wreg[2 * i + 1], x1); }
        }
        float2 s0 = unpack2(a0), s1 = unpack2(a1), s2 = unpack2(a2), s3 = unpack2(a3);
        float part = ((s0.x + s0.y) + (s1.x + s1.y)) + ((s2.x + s2.y) + (s3.x + s3.y));
        part += __shfl_xor_sync(0xFFFFFFFFu, part, 16);   // combine lane pair

        if (!own) {
            // push full k-half partial for peer-owned row jl
            if (lhalf) {
                uint32_t ra = recv_peer + (uint32_t)((p * 128 + jl) * 4);
                asm volatile("st.shared::cluster.f32 [%0], %1;" :: "r"(ra), "f"(part) : "memory");
            }
            __syncwarp();
            if (lane == 0) {
                asm volatile("mbarrier.arrive.release.cluster.shared::cluster.b64 _, [%0];"
                             :: "r"(mb_peer + (uint32_t)(p * 8)) : "memory");
            }
        } else {
            // wait for peer's 8 pusher warps, then finalize
            if (p) { mbar_wait_cluster(mb_local + 8, ph1); ph1 ^= 1; }
            else   { mbar_wait_cluster(mb_local,     ph0); ph0 ^= 1; }
            if (lhalf) {
                float s = part + recv_sm[p][jl] + acur;
                float hv = tanh_fast(s);
                h_sm[p ^ 1][jl] = hv;
                Hbase[(size_t)t * (BATCH * HID)] = hv;
            }
        }
        __syncthreads();  // new h visible; closes reuse window on phase-p buffers
    }
    cluster_sync_();  // keep smem alive for in-flight peer traffic
}

// ---------------- launcher ----------------
extern "C" void kernel_launch(void* const* d_in, const int* in_sizes, int n_in,
                              void* d_out, int out_size) {
    const float* x    = (const float*)d_in[0];
    const float* U0   = (const float*)d_in[1];
    const float* bU0  = (const float*)d_in[2];
    const float* W0   = (const float*)d_in[3];
    const float* bW0  = (const float*)d_in[4];
    const float* U1   = (const float*)d_in[5];
    const float* bU1  = (const float*)d_in[6];
    const float* W1   = (const float*)d_in[7];
    const float* bW1  = (const float*)d_in[8];
    const float* fc1W = (const float*)d_in[9];
    const float* fc1b = (const float*)d_in[10];
    const float* fc2W = (const float*)d_in[11];
    const float* fc2b = (const float*)d_in[12];
    const float* fc3W = (const float*)d_in[13];
    const float* fc3b = (const float*)d_in[14];
    float* out = (float*)d_out;

    float *pA, *pH, *pWc, *pbc;
    cudaGetSymbolAddress((void**)&pA, g_bufA);
    cudaGetSymbolAddress((void**)&pH, g_bufH);
    cudaGetSymbolAddress((void**)&pWc, g_Wc);
    cudaGetSymbolAddress((void**)&pbc, g_bc);

    combine1_kernel<<<HID, HID>>>(fc2W, fc1W, fc1b, fc2b);
    combine2_kernel<<<OUTD, HID>>>(fc3W, fc3b);

    // A0[t,b,:] = x[b,t,:] @ U0^T + bU0 + bW0
    gemm_kernel<128, 8, 1, 0><<<dim3(M_ROWS / 128, HID / 128), 256>>>(x, U0, bU0, bW0, pA, IND);
    scan_kernel<<<BATCH * 2, 512>>>(pA, W0, pH);
    // A1 = h0_all @ U1^T + bU1 + bW1
    gemm_kernel<128, 8, 0, 0><<<dim3(M_ROWS / 128, HID / 128), 256>>>(pH, U1, bU1, bW1, pA, HID);
    scan_kernel<<<BATCH * 2, 512>>>(pA, W1, pH);
    // head: out[b,t,:] = outs[t,b,:] @ Wc^T + bc (N=64)
    gemm_kernel<64, 4, 0, 1><<<dim3(M_ROWS / 128, 1), 256>>>(pH, pWc, pbc, nullptr, out, HID);
}

// round 8
// speedup vs baseline: 2.1175x; 1.5316x over previous
#include <cuda_runtime.h>
#include <cstdint>
#include <cstddef>

#define BATCH 64
#define SEQ   2048
#define IND   128
#define HID   256
#define OUTD  64
#define M_ROWS (SEQ*BATCH)

typedef unsigned long long ull;

// ---------------- scratch ----------------
__device__ float g_bufA[(size_t)SEQ * BATCH * HID];
__device__ float g_bufH[(size_t)SEQ * BATCH * HID];
__device__ float g_T1[HID * HID];
__device__ float g_Wc[OUTD * HID];
__device__ float g_b12[HID];
__device__ float g_bc[OUTD];

// ---------------- f32x2 helpers ----------------
__device__ __forceinline__ void ffma2(ull& acc, ull a, ull b) {
    asm("fma.rn.f32x2 %0, %1, %2, %0;" : "+l"(acc) : "l"(a), "l"(b));
}
__device__ __forceinline__ ull pack2(float x, float y) {
    ull r; asm("mov.b64 %0, {%1,%2};" : "=l"(r) : "f"(x), "f"(y)); return r;
}
__device__ __forceinline__ float2 unpack2(ull v) {
    float2 r; asm("mov.b64 {%0,%1}, %2;" : "=f"(r.x), "=f"(r.y) : "l"(v)); return r;
}
__device__ __forceinline__ void lds_v2u64(ull& a, ull& b, uint32_t addr) {
    asm volatile("ld.shared.v2.u64 {%0,%1}, [%2];" : "=l"(a), "=l"(b) : "r"(addr));
}
// fast tanh: 1 - 2/(exp(2x)+1); MUFU-based, rel err ~1e-6, saturates correctly
__device__ __forceinline__ float tanh_fast(float x) {
    float e = __expf(2.f * x);
    return 1.f - __fdividef(2.f, e + 1.f);
}

// ---------------- head folding ----------------
__global__ void combine1_kernel(const float* __restrict__ fc2W, const float* __restrict__ fc1W,
                                const float* __restrict__ fc1b, const float* __restrict__ fc2b) {
    int i = blockIdx.x, k = threadIdx.x;
    float acc = 0.f;
    for (int j = 0; j < HID; ++j) acc += fc2W[i * HID + j] * fc1W[j * HID + k];
    g_T1[i * HID + k] = acc;
    if (k == 0) {
        float s = 0.f;
        for (int j = 0; j < HID; ++j) s += fc2W[i * HID + j] * fc1b[j];
        g_b12[i] = s + fc2b[i];
    }
}
__global__ void combine2_kernel(const float* __restrict__ fc3W, const float* __restrict__ fc3b) {
    int o = blockIdx.x, k = threadIdx.x;
    float acc = 0.f;
    for (int j = 0; j < HID; ++j) acc += fc3W[o * HID + j] * g_T1[j * HID + k];
    g_Wc[o * HID + k] = acc;
    if (k == 0) {
        float s = 0.f;
        for (int j = 0; j < HID; ++j) s += fc3W[o * HID + j] * g_b12[j];
        g_bc[o] = s + fc3b[o];
    }
}

// ---------------- f32x2 SIMT GEMM (unchanged) ----------------
template<int TN, int MT, int AMODE, int OMODE>
__global__ void __launch_bounds__(256)
gemm_kernel(const float* __restrict__ Ap, const float* __restrict__ Bw,
            const float* __restrict__ bias1, const float* __restrict__ bias2,
            float* __restrict__ Cp, int K) {
    __shared__ __align__(16) float As[16][128];
    __shared__ __align__(16) float Bs[16][TN];
    constexpr int NX = TN / 8;
    const int tid = threadIdx.x;
    const int bm = blockIdx.x * 128;
    const int bn = blockIdx.y * TN;
    const int tx = tid % NX, ty = tid / NX;

    const float* arow[2]; int amm[2], akq[2];
#pragma unroll
    for (int it = 0; it < 2; ++it) {
        int slot = tid + it * 256;
        amm[it] = slot >> 2; akq[it] = slot & 3;
        int m = bm + amm[it];
        if (AMODE) arow[it] = Ap + ((size_t)(m & 63) * SEQ + (m >> 6)) * K;
        else       arow[it] = Ap + (size_t)m * K;
    }
    constexpr int BLD = TN / 64;
    const float* brow[BLD]; int bnn[BLD], bkq[BLD];
#pragma unroll
    for (int it = 0; it < BLD; ++it) {
        int slot = tid + it * 256;
        bnn[it] = slot >> 2; bkq[it] = slot & 3;
        brow[it] = Bw + (size_t)(bn + bnn[it]) * K;
    }

    ull acc[MT][4];
#pragma unroll
    for (int i = 0; i < MT; ++i)
#pragma unroll
        for (int j = 0; j < 4; ++j) acc[i][j] = 0ull;

    uint32_t bs_base = (uint32_t)__cvta_generic_to_shared(&Bs[0][0]);

    for (int k0 = 0; k0 < K; k0 += 16) {
#pragma unroll
        for (int it = 0; it < 2; ++it) {
            float4 v = *(const float4*)(arow[it] + k0 + akq[it] * 4);
            As[akq[it] * 4 + 0][amm[it]] = v.x;
            As[akq[it] * 4 + 1][amm[it]] = v.y;
            As[akq[it] * 4 + 2][amm[it]] = v.z;
            As[akq[it] * 4 + 3][amm[it]] = v.w;
        }
#pragma unroll
        for (int it = 0; it < BLD; ++it) {
            float4 v = *(const float4*)(brow[it] + k0 + bkq[it] * 4);
            Bs[bkq[it] * 4 + 0][bnn[it]] = v.x;
            Bs[bkq[it] * 4 + 1][bnn[it]] = v.y;
            Bs[bkq[it] * 4 + 2][bnn[it]] = v.z;
            Bs[bkq[it] * 4 + 3][bnn[it]] = v.w;
        }
        __syncthreads();
#pragma unroll
        for (int kk = 0; kk < 16; ++kk) {
            ull b0, b1, b2, b3;
            uint32_t ba = bs_base + (uint32_t)((kk * TN + tx * 8) * 4);
            lds_v2u64(b0, b1, ba);
            lds_v2u64(b2, b3, ba + 16);
            float av[MT];
#pragma unroll
            for (int q = 0; q < MT; q += 4) {
                float4 a4 = *(const float4*)&As[kk][ty * MT + q];
                av[q] = a4.x; av[q + 1] = a4.y; av[q + 2] = a4.z; av[q + 3] = a4.w;
            }
#pragma unroll
            for (int i = 0; i < MT; ++i) {
                ull ad = pack2(av[i], av[i]);
                ffma2(acc[i][0], ad, b0);
                ffma2(acc[i][1], ad, b1);
                ffma2(acc[i][2], ad, b2);
                ffma2(acc[i][3], ad, b3);
            }
        }
        __syncthreads();
    }

    float bb[8];
#pragma unroll
    for (int j = 0; j < 8; ++j) {
        int n = bn + tx * 8 + j;
        float v = bias1 ? bias1[n] : 0.f;
        if (bias2) v += bias2[n];
        bb[j] = v;
    }
#pragma unroll
    for (int i = 0; i < MT; ++i) {
        int m = bm + ty * MT + i;
        float2 p0 = unpack2(acc[i][0]), p1 = unpack2(acc[i][1]);
        float2 p2 = unpack2(acc[i][2]), p3 = unpack2(acc[i][3]);
        float4 v0 = {p0.x + bb[0], p0.y + bb[1], p1.x + bb[2], p1.y + bb[3]};
        float4 v1 = {p2.x + bb[4], p2.y + bb[5], p3.x + bb[6], p3.y + bb[7]};
        float* dst;
        if (OMODE) dst = Cp + ((size_t)(m & 63) * SEQ + (m >> 6)) * OUTD + bn + tx * 8;
        else       dst = Cp + (size_t)m * ((size_t)gridDim.y * TN) + bn + tx * 8;
        *(float4*)dst = v0;
        *(float4*)(dst + 4) = v1;
    }
}

// ---------------- persistent RNN scan: fence-free epoch-packed exchange ----------------
// 2-CTA cluster per batch, 256 threads. Thread tid owns full row tid with the
// local 128-wide k-half of W in registers (R4 layout). Cross-CTA exchange is a
// single relaxed 64-bit store per row: {f32 partial | u32 epoch}. The consumer
// spins on the word until epoch==t — data and flag are one atom, NO fences,
// NO mbarrier. recv slots double-buffered by t&1 (one full step of slack).
__device__ __forceinline__ void cluster_sync_() {
    asm volatile("barrier.cluster.arrive.aligned;" ::: "memory");
    asm volatile("barrier.cluster.wait.aligned;" ::: "memory");
}

__global__ void __cluster_dims__(2, 1, 1) __launch_bounds__(256, 1)
scan_kernel(const float* __restrict__ A, const float* __restrict__ W, float* __restrict__ Hout) {
    __shared__ __align__(16) float h_sm[2][128];    // local h half, double buffered
    __shared__ __align__(16) ull recv_sm[2][128];   // {partial,epoch} per own row, by t&1
    const int tid = threadIdx.x;
    uint32_t rank;
    asm("mov.u32 %0, %%cluster_ctarank;" : "=r"(rank));
    const int b = blockIdx.x >> 1;
    const int jl = tid & 127;
    const bool own = ((uint32_t)(tid >> 7) == rank);   // warp-uniform

    // register-resident W slice: row tid, k in [rank*128, rank*128+128)
    ull wreg[64];
    {
        const float* ws = W + (size_t)tid * HID + rank * 128;
#pragma unroll
        for (int i = 0; i < 64; i += 2) {
            float4 v = *(const float4*)(ws + i * 2);
            wreg[i] = pack2(v.x, v.y); wreg[i + 1] = pack2(v.z, v.w);
        }
    }

    uint32_t h_local = (uint32_t)__cvta_generic_to_shared(&h_sm[0][0]);
    uint32_t recv_local = (uint32_t)__cvta_generic_to_shared(&recv_sm[0][0]);
    uint32_t recv_peer;
    asm("mapa.shared::cluster.u32 %0, %1, %2;" : "=r"(recv_peer) : "r"(recv_local), "r"(rank ^ 1u));

    // init epochs to sentinel (never matches t in [1, SEQ))
    if (tid < 128) {
        recv_sm[0][tid] = 0xFFFFFFFF00000000ull;
        recv_sm[1][tid] = 0xFFFFFFFF00000000ull;
    }
    __syncthreads();
    cluster_sync_();   // peer recv buffers initialized before any incoming store

    const float* Abase = A + (size_t)b * HID + tid;   // only used by own rows
    float* Hbase = Hout + (size_t)b * HID + tid;

    float acur = 0.f, anext = 0.f;
    // ---- t = 0: h = tanh(A[0]) ----
    if (own) {
        acur = __ldg(Abase);
        float hv = tanh_fast(acur);
        h_sm[1][jl] = hv;
        Hbase[0] = hv;
        anext = __ldg(Abase + (size_t)BATCH * HID);
    }
    __syncthreads();

    for (int t = 1; t < SEQ; ++t) {
        const int p = t & 1;
        acur = anext;
        if (own) {
            int tn = (t + 1 < SEQ) ? (t + 1) : (SEQ - 1);
            anext = __ldg(Abase + (size_t)tn * (BATCH * HID));
        }
        // ---- dot over local 128-wide h-half (h[t-1] in h_sm[p]) ----
        uint32_t hb = h_local + (uint32_t)(p * 128 * 4);
        ull a0 = 0ull, a1 = 0ull, a2 = 0ull, a3 = 0ull;
#pragma unroll
        for (int i = 0; i < 32; ++i) {           // 32 iters x 4 floats = 128 h values
            ull x0, x1;
            lds_v2u64(x0, x1, hb + (uint32_t)(i * 16));
            if (i & 1) { ffma2(a2, wreg[2 * i], x0); ffma2(a3, wreg[2 * i + 1], x1); }
            else       { ffma2(a0, wreg[2 * i], x0); ffma2(a1, wreg[2 * i + 1], x1); }
        }
        float2 s0 = unpack2(a0), s1 = unpack2(a1), s2 = unpack2(a2), s3 = unpack2(a3);
        float part = ((s0.x + s0.y) + (s1.x + s1.y)) + ((s2.x + s2.y) + (s3.x + s3.y));

        if (!own) {
            // single relaxed 64-bit store: {epoch=t | partial}; no fence, no arrive
            ull msg;
            asm("mov.b64 %0, {%1,%2};" : "=l"(msg) : "r"(__float_as_uint(part)), "r"((uint32_t)t));
            uint32_t ra = recv_peer + (uint32_t)((p * 128 + jl) * 8);
            asm volatile("st.relaxed.cluster.shared::cluster.b64 [%0], %1;"
                         :: "r"(ra), "l"(msg) : "memory");
        } else {
            // spin until the epoch word equals t (data rides in the same atom)
            uint32_t ra = recv_local + (uint32_t)((p * 128 + jl) * 8);
            ull v;
            do {
                asm volatile("ld.relaxed.cluster.shared::cta.b64 %0, [%1];" : "=l"(v) : "r"(ra));
            } while ((uint32_t)(v >> 32) != (uint32_t)t);
            float rpart = __uint_as_float((uint32_t)v);
            float s = part + rpart + acur;
            float hv = tanh_fast(s);
            h_sm[p ^ 1][jl] = hv;
            Hbase[(size_t)t * (BATCH * HID)] = hv;
        }
        __syncthreads();  // new local h visible to pusher warps; closes phase-p window
    }
    cluster_sync_();  // keep smem alive for any in-flight peer traffic
}

// ---------------- launcher ----------------
extern "C" void kernel_launch(void* const* d_in, const int* in_sizes, int n_in,
                              void* d_out, int out_size) {
    const float* x    = (const float*)d_in[0];
    const float* U0   = (const float*)d_in[1];
    const float* bU0  = (const float*)d_in[2];
    const float* W0   = (const float*)d_in[3];
    const float* bW0  = (const float*)d_in[4];
    const float* U1   = (const float*)d_in[5];
    const float* bU1  = (const float*)d_in[6];
    const float* W1   = (const float*)d_in[7];
    const float* bW1  = (const float*)d_in[8];
    const float* fc1W = (const float*)d_in[9];
    const float* fc1b = (const float*)d_in[10];
    const float* fc2W = (const float*)d_in[11];
    const float* fc2b = (const float*)d_in[12];
    const float* fc3W = (const float*)d_in[13];
    const float* fc3b = (const float*)d_in[14];
    float* out = (float*)d_out;

    float *pA, *pH, *pWc, *pbc;
    cudaGetSymbolAddress((void**)&pA, g_bufA);
    cudaGetSymbolAddress((void**)&pH, g_bufH);
    cudaGetSymbolAddress((void**)&pWc, g_Wc);
    cudaGetSymbolAddress((void**)&pbc, g_bc);

    combine1_kernel<<<HID, HID>>>(fc2W, fc1W, fc1b, fc2b);
    combine2_kernel<<<OUTD, HID>>>(fc3W, fc3b);

    // A0[t,b,:] = x[b,t,:] @ U0^T + bU0 + bW0
    gemm_kernel<128, 8, 1, 0><<<dim3(M_ROWS / 128, HID / 128), 256>>>(x, U0, bU0, bW0, pA, IND);
    scan_kernel<<<BATCH * 2, 256>>>(pA, W0, pH);
    // A1 = h0_all @ U1^T + bU1 + bW1
    gemm_kernel<128, 8, 0, 0><<<dim3(M_ROWS / 128, HID / 128), 256>>>(pH, U1, bU1, bW1, pA, HID);
    scan_kernel<<<BATCH * 2, 256>>>(pA, W1, pH);
    // head: out[b,t,:] = outs[t,b,:] @ Wc^T + bc (N=64)
    gemm_kernel<64, 4, 0, 1><<<dim3(M_ROWS / 128, 1), 256>>>(pH, pWc, pbc, nullptr, out, HID);
}

// round 9
// speedup vs baseline: 2.1640x; 1.0220x over previous
#include <cuda_runtime.h>
#include <cstdint>
#include <cstddef>

#define BATCH 64
#define SEQ   2048
#define IND   128
#define HID   256
#define OUTD  64
#define M_ROWS (SEQ*BATCH)

typedef unsigned long long ull;

// ---------------- scratch ----------------
__device__ float g_bufA[(size_t)SEQ * BATCH * HID];
__device__ float g_bufH[(size_t)SEQ * BATCH * HID];
__device__ float g_T1[HID * HID];
__device__ float g_Wc[OUTD * HID];
__device__ float g_b12[HID];
__device__ float g_bc[OUTD];

// ---------------- f32x2 helpers ----------------
__device__ __forceinline__ void ffma2(ull& acc, ull a, ull b) {
    asm("fma.rn.f32x2 %0, %1, %2, %0;" : "+l"(acc) : "l"(a), "l"(b));
}
__device__ __forceinline__ ull pack2(float x, float y) {
    ull r; asm("mov.b64 %0, {%1,%2};" : "=l"(r) : "f"(x), "f"(y)); return r;
}
__device__ __forceinline__ float2 unpack2(ull v) {
    float2 r; asm("mov.b64 {%0,%1}, %2;" : "=f"(r.x), "=f"(r.y) : "l"(v)); return r;
}
__device__ __forceinline__ void lds_v2u64(ull& a, ull& b, uint32_t addr) {
    asm volatile("ld.shared.v2.u64 {%0,%1}, [%2];" : "=l"(a), "=l"(b) : "r"(addr));
}
// fast tanh: 1 - 2/(exp(2x)+1); MUFU-based, rel err ~1e-6, saturates correctly
__device__ __forceinline__ float tanh_fast(float x) {
    float e = __expf(2.f * x);
    return 1.f - __fdividef(2.f, e + 1.f);
}

// ---------------- head folding ----------------
__global__ void combine1_kernel(const float* __restrict__ fc2W, const float* __restrict__ fc1W,
                                const float* __restrict__ fc1b, const float* __restrict__ fc2b) {
    int i = blockIdx.x, k = threadIdx.x;
    float acc = 0.f;
    for (int j = 0; j < HID; ++j) acc += fc2W[i * HID + j] * fc1W[j * HID + k];
    g_T1[i * HID + k] = acc;
    if (k == 0) {
        float s = 0.f;
        for (int j = 0; j < HID; ++j) s += fc2W[i * HID + j] * fc1b[j];
        g_b12[i] = s + fc2b[i];
    }
}
__global__ void combine2_kernel(const float* __restrict__ fc3W, const float* __restrict__ fc3b) {
    int o = blockIdx.x, k = threadIdx.x;
    float acc = 0.f;
    for (int j = 0; j < HID; ++j) acc += fc3W[o * HID + j] * g_T1[j * HID + k];
    g_Wc[o * HID + k] = acc;
    if (k == 0) {
        float s = 0.f;
        for (int j = 0; j < HID; ++j) s += fc3W[o * HID + j] * g_b12[j];
        g_bc[o] = s + fc3b[o];
    }
}

// ---------------- f32x2 SIMT GEMM, double-buffered smem ----------------
// C[m][n] = sum_k A[m][k]*Bw[n][k] + bias. BM=128, BN=TN, BK=16, 256 threads.
template<int TN, int MT, int AMODE, int OMODE>
__global__ void __launch_bounds__(256)
gemm_kernel(const float* __restrict__ Ap, const float* __restrict__ Bw,
            const float* __restrict__ bias1, const float* __restrict__ bias2,
            float* __restrict__ Cp, int K) {
    __shared__ __align__(16) float As[2][16][128];
    __shared__ __align__(16) float Bs[2][16][TN];
    constexpr int NX = TN / 8;
    constexpr int BLD = TN / 64;
    const int tid = threadIdx.x;
    const int bm = blockIdx.x * 128;
    const int bn = blockIdx.y * TN;
    const int tx = tid % NX, ty = tid / NX;

    const float* arow[2]; int amm[2], akq[2];
#pragma unroll
    for (int it = 0; it < 2; ++it) {
        int slot = tid + it * 256;
        amm[it] = slot >> 2; akq[it] = slot & 3;
        int m = bm + amm[it];
        if (AMODE) arow[it] = Ap + ((size_t)(m & 63) * SEQ + (m >> 6)) * K;
        else       arow[it] = Ap + (size_t)m * K;
    }
    const float* brow[BLD]; int bnn[BLD], bkq[BLD];
#pragma unroll
    for (int it = 0; it < BLD; ++it) {
        int slot = tid + it * 256;
        bnn[it] = slot >> 2; bkq[it] = slot & 3;
        brow[it] = Bw + (size_t)(bn + bnn[it]) * K;
    }

    ull acc[MT][4];
#pragma unroll
    for (int i = 0; i < MT; ++i)
#pragma unroll
        for (int j = 0; j < 4; ++j) acc[i][j] = 0ull;

    // prologue: tile 0 -> smem[0]
    {
#pragma unroll
        for (int it = 0; it < 2; ++it) {
            float4 v = *(const float4*)(arow[it] + akq[it] * 4);
            As[0][akq[it] * 4 + 0][amm[it]] = v.x;
            As[0][akq[it] * 4 + 1][amm[it]] = v.y;
            As[0][akq[it] * 4 + 2][amm[it]] = v.z;
            As[0][akq[it] * 4 + 3][amm[it]] = v.w;
        }
#pragma unroll
        for (int it = 0; it < BLD; ++it) {
            float4 v = *(const float4*)(brow[it] + bkq[it] * 4);
            Bs[0][bkq[it] * 4 + 0][bnn[it]] = v.x;
            Bs[0][bkq[it] * 4 + 1][bnn[it]] = v.y;
            Bs[0][bkq[it] * 4 + 2][bnn[it]] = v.z;
            Bs[0][bkq[it] * 4 + 3][bnn[it]] = v.w;
        }
    }
    __syncthreads();

    uint32_t bs0 = (uint32_t)__cvta_generic_to_shared(&Bs[0][0][0]);

    for (int k0 = 0; k0 < K; k0 += 16) {
        const int buf = (k0 >> 4) & 1;
        const bool hasNext = (k0 + 16) < K;
        float4 pa[2], pb[BLD];
        if (hasNext) {
#pragma unroll
            for (int it = 0; it < 2; ++it)
                pa[it] = *(const float4*)(arow[it] + k0 + 16 + akq[it] * 4);
#pragma unroll
            for (int it = 0; it < BLD; ++it)
                pb[it] = *(const float4*)(brow[it] + k0 + 16 + bkq[it] * 4);
        }
        uint32_t bs_base = bs0 + (uint32_t)(buf * 16 * TN * 4);
#pragma unroll
        for (int kk = 0; kk < 16; ++kk) {
            ull b0, b1, b2, b3;
            uint32_t ba = bs_base + (uint32_t)((kk * TN + tx * 8) * 4);
            lds_v2u64(b0, b1, ba);
            lds_v2u64(b2, b3, ba + 16);
            float av[MT];
#pragma unroll
            for (int q = 0; q < MT; q += 4) {
                float4 a4 = *(const float4*)&As[buf][kk][ty * MT + q];
                av[q] = a4.x; av[q + 1] = a4.y; av[q + 2] = a4.z; av[q + 3] = a4.w;
            }
#pragma unroll
            for (int i = 0; i < MT; ++i) {
                ull ad = pack2(av[i], av[i]);
                ffma2(acc[i][0], ad, b0);
                ffma2(acc[i][1], ad, b1);
                ffma2(acc[i][2], ad, b2);
                ffma2(acc[i][3], ad, b3);
            }
        }
        if (hasNext) {
            const int nb = buf ^ 1;
#pragma unroll
            for (int it = 0; it < 2; ++it) {
                As[nb][akq[it] * 4 + 0][amm[it]] = pa[it].x;
                As[nb][akq[it] * 4 + 1][amm[it]] = pa[it].y;
                As[nb][akq[it] * 4 + 2][amm[it]] = pa[it].z;
                As[nb][akq[it] * 4 + 3][amm[it]] = pa[it].w;
            }
#pragma unroll
            for (int it = 0; it < BLD; ++it) {
                Bs[nb][bkq[it] * 4 + 0][bnn[it]] = pb[it].x;
                Bs[nb][bkq[it] * 4 + 1][bnn[it]] = pb[it].y;
                Bs[nb][bkq[it] * 4 + 2][bnn[it]] = pb[it].z;
                Bs[nb][bkq[it] * 4 + 3][bnn[it]] = pb[it].w;
            }
        }
        __syncthreads();
    }

    float bb[8];
#pragma unroll
    for (int j = 0; j < 8; ++j) {
        int n = bn + tx * 8 + j;
        float v = bias1 ? bias1[n] : 0.f;
        if (bias2) v += bias2[n];
        bb[j] = v;
    }
#pragma unroll
    for (int i = 0; i < MT; ++i) {
        int m = bm + ty * MT + i;
        float2 p0 = unpack2(acc[i][0]), p1 = unpack2(acc[i][1]);
        float2 p2 = unpack2(acc[i][2]), p3 = unpack2(acc[i][3]);
        float4 v0 = {p0.x + bb[0], p0.y + bb[1], p1.x + bb[2], p1.y + bb[3]};
        float4 v1 = {p2.x + bb[4], p2.y + bb[5], p3.x + bb[6], p3.y + bb[7]};
        float* dst;
        if (OMODE) dst = Cp + ((size_t)(m & 63) * SEQ + (m >> 6)) * OUTD + bn + tx * 8;
        else       dst = Cp + (size_t)m * ((size_t)gridDim.y * TN) + bn + tx * 8;
        *(float4*)dst = v0;
        *(float4*)(dst + 4) = v1;
    }
}

// ---------------- persistent RNN scan: fence-free epoch-packed exchange ----------------
// 2-CTA cluster per batch, 256 threads. Thread tid owns full row tid with the
// local 128-wide k-half of W in registers. Cross-CTA exchange is one relaxed
// 64-bit store per row: {f32 partial | u32 epoch}; consumer spins with plain
// volatile LDS (data and flag are one atom -> no fences, no mbarrier).
// Pusher warps (idle after send) handle the Hout global store, one step delayed,
// keeping STG off the owner's critical path.
__device__ __forceinline__ void cluster_sync_() {
    asm volatile("barrier.cluster.arrive.aligned;" ::: "memory");
    asm volatile("barrier.cluster.wait.aligned;" ::: "memory");
}

__global__ void __cluster_dims__(2, 1, 1) __launch_bounds__(256, 1)
scan_kernel(const float* __restrict__ A, const float* __restrict__ W, float* __restrict__ Hout) {
    __shared__ __align__(16) float h_sm[2][128];    // local h half, double buffered
    __shared__ __align__(16) ull recv_sm[2][128];   // {partial,epoch} per own row, by t&1
    const int tid = threadIdx.x;
    uint32_t rank;
    asm("mov.u32 %0, %%cluster_ctarank;" : "=r"(rank));
    const int b = blockIdx.x >> 1;
    const int jl = tid & 127;
    const bool own = ((uint32_t)(tid >> 7) == rank);   // warp-uniform

    // register-resident W slice: row tid, k in [rank*128, rank*128+128)
    ull wreg[64];
    {
        const float* ws = W + (size_t)tid * HID + rank * 128;
#pragma unroll
        for (int i = 0; i < 64; i += 2) {
            float4 v = *(const float4*)(ws + i * 2);
            wreg[i] = pack2(v.x, v.y); wreg[i + 1] = pack2(v.z, v.w);
        }
    }

    uint32_t h_local = (uint32_t)__cvta_generic_to_shared(&h_sm[0][0]);
    uint32_t recv_local = (uint32_t)__cvta_generic_to_shared(&recv_sm[0][0]);
    uint32_t recv_peer;
    asm("mapa.shared::cluster.u32 %0, %1, %2;" : "=r"(recv_peer) : "r"(recv_local), "r"(rank ^ 1u));

    // init epochs to sentinel (never matches t in [1, SEQ))
    if (tid < 128) {
        recv_sm[0][tid] = 0xFFFFFFFF00000000ull;
        recv_sm[1][tid] = 0xFFFFFFFF00000000ull;
    }
    __syncthreads();
    cluster_sync_();   // peer recv buffers initialized before any incoming store

    const float* Abase = A + (size_t)b * HID + tid;            // own rows only
    float* Hown = Hout + (size_t)b * HID + rank * 128 + jl;    // pusher-writes local half

    float acur = 0.f, anext = 0.f;
    // ---- t = 0: h = tanh(A[0]) ----
    if (own) {
        acur = __ldg(Abase);
        float hv = tanh_fast(acur);
        h_sm[1][jl] = hv;
        anext = __ldg(Abase + (size_t)BATCH * HID);
    }
    __syncthreads();

    for (int t = 1; t < SEQ; ++t) {
        const int p = t & 1;
        acur = anext;
        if (own) {
            int tn = (t + 1 < SEQ) ? (t + 1) : (SEQ - 1);
            anext = __ldg(Abase + (size_t)tn * (BATCH * HID));
        }
        // ---- dot over local 128-wide h-half (h[t-1] in h_sm[p]) ----
        uint32_t hb = h_local + (uint32_t)(p * 128 * 4);
        ull a0 = 0ull, a1 = 0ull, a2 = 0ull, a3 = 0ull;
#pragma unroll
        for (int i = 0; i < 32; ++i) {
            ull x0, x1;
            lds_v2u64(x0, x1, hb + (uint32_t)(i * 16));
            if (i & 1) { ffma2(a2, wreg[2 * i], x0); ffma2(a3, wreg[2 * i + 1], x1); }
            else       { ffma2(a0, wreg[2 * i], x0); ffma2(a1, wreg[2 * i + 1], x1); }
        }
        float2 s0 = unpack2(a0), s1 = unpack2(a1), s2 = unpack2(a2), s3 = unpack2(a3);
        float part = ((s0.x + s0.y) + (s1.x + s1.y)) + ((s2.x + s2.y) + (s3.x + s3.y));

        if (!own) {
            // single relaxed 64-bit store: {epoch=t | partial}; no fence, no arrive
            ull msg;
            asm("mov.b64 %0, {%1,%2};" : "=l"(msg) : "r"(__float_as_uint(part)), "r"((uint32_t)t));
            uint32_t ra = recv_peer + (uint32_t)((p * 128 + jl) * 8);
            asm volatile("st.relaxed.cluster.shared::cluster.b64 [%0], %1;"
                         :: "r"(ra), "l"(msg) : "memory");
            // delayed global store of h[t-1] (off owner's critical path)
            float hprev = h_sm[p][jl];
            Hown[(size_t)(t - 1) * (BATCH * HID)] = hprev;
        } else {
            // spin on the epoch word (plain volatile LDS; data rides in same atom)
            uint32_t ra = recv_local + (uint32_t)((p * 128 + jl) * 8);
            ull v;
            do {
                asm volatile("ld.volatile.shared.b64 %0, [%1];" : "=l"(v) : "r"(ra));
            } while ((uint32_t)(v >> 32) != (uint32_t)t);
            float rpart = __uint_as_float((uint32_t)v);
            float s = part + rpart + acur;
            float hv = tanh_fast(s);
            h_sm[p ^ 1][jl] = hv;
        }
        __syncthreads();  // new local h visible to pushers; closes phase-p window
    }
    // epilogue: store h[SEQ-1] (lives in h_sm[0] since SEQ is even)
    if (!own) {
        Hown[(size_t)(SEQ - 1) * (BATCH * HID)] = h_sm[0][jl];
    }
    cluster_sync_();  // keep smem alive for any in-flight peer traffic
}

// ---------------- launcher ----------------
extern "C" void kernel_launch(void* const* d_in, const int* in_sizes, int n_in,
                              void* d_out, int out_size) {
    const float* x    = (const float*)d_in[0];
    const float* U0   = (const float*)d_in[1];
    const float* bU0  = (const float*)d_in[2];
    const float* W0   = (const float*)d_in[3];
    const float* bW0  = (const float*)d_in[4];
    const float* U1   = (const float*)d_in[5];
    const float* bU1  = (const float*)d_in[6];
    const float* W1   = (const float*)d_in[7];
    const float* bW1  = (const float*)d_in[8];
    const float* fc1W = (const float*)d_in[9];
    const float* fc1b = (const float*)d_in[10];
    const float* fc2W = (const float*)d_in[11];
    const float* fc2b = (const float*)d_in[12];
    const float* fc3W = (const float*)d_in[13];
    const float* fc3b = (const float*)d_in[14];
    float* out = (float*)d_out;

    float *pA, *pH, *pWc, *pbc;
    cudaGetSymbolAddress((void**)&pA, g_bufA);
    cudaGetSymbolAddress((void**)&pH, g_bufH);
    cudaGetSymbolAddress((void**)&pWc, g_Wc);
    cudaGetSymbolAddress((void**)&pbc, g_bc);

    combine1_kernel<<<HID, HID>>>(fc2W, fc1W, fc1b, fc2b);
    combine2_kernel<<<OUTD, HID>>>(fc3W, fc3b);

    // A0[t,b,:] = x[b,t,:] @ U0^T + bU0 + bW0
    gemm_kernel<128, 8, 1, 0><<<dim3(M_ROWS / 128, HID / 128), 256>>>(x, U0, bU0, bW0, pA, IND);
    scan_kernel<<<BATCH * 2, 256>>>(pA, W0, pH);
    // A1 = h0_all @ U1^T + bU1 + bW1
    gemm_kernel<128, 8, 0, 0><<<dim3(M_ROWS / 128, HID / 128), 256>>>(pH, U1, bU1, bW1, pA, HID);
    scan_kernel<<<BATCH * 2, 256>>>(pA, W1, pH);
    // head: out[b,t,:] = outs[t,b,:] @ Wc^T + bc (N=64)
    gemm_kernel<64, 4, 0, 1><<<dim3(M_ROWS / 128, 1), 256>>>(pH, pWc, pbc, nullptr, out, HID);
}